// round 13
// baseline (speedup 1.0000x reference)
#include <cuda_runtime.h>

#define NN   20000
#define FF   4
#define TT   12
#define CC   256
#define HIDN 128
#define OUTN 12
#define ERN  30000
#define NREG 5
#define FT   48   // F*T floats per node
#define GNB  8    // nodes per gate block
#define MNB  32   // nodes per MLP block

typedef unsigned long long u64;

struct RegPtrs { const int* ei[NREG]; const float* ew[NREG]; };

// ---------------------------------------------------------------- helpers
__device__ __forceinline__ u64 pack2(float lo, float hi) {
    u64 r; asm("mov.b64 %0,{%1,%2};" : "=l"(r) : "f"(lo), "f"(hi)); return r;
}
__device__ __forceinline__ void unpack2(u64 v, float& lo, float& hi) {
    asm("mov.b64 {%0,%1},%2;" : "=f"(lo), "=f"(hi) : "l"(v));
}
__device__ __forceinline__ u64 ffma2(u64 a, u64 b, u64 c) {
    u64 d; asm("fma.rn.f32x2 %0,%1,%2,%3;" : "=l"(d) : "l"(a), "l"(b), "l"(c)); return d;
}
__device__ __forceinline__ float tanh_fast(float x) {
    float r; asm("tanh.approx.f32 %0,%1;" : "=f"(r) : "f"(x)); return r;
}
__device__ __forceinline__ void red4(float4* p, float a, float b, float c, float d) {
    asm volatile("red.global.add.v4.f32 [%0], {%1,%2,%3,%4};"
                 :: "l"(p), "f"(a), "f"(b), "f"(c), "f"(d) : "memory");
}

// ---------------------------------------------------------------- scratch
__device__ float g_deg[NREG * NN];
__device__ __align__(16) float g_y[NN * FT];   // message accumulator [N, F, T]
__device__ float g_Mz[FF * CC];                // 0.5 * Wc_z@Wl_z[:C]
__device__ float g_Mh[FF * CC];                // Wc_h@Wl_h[:C]
__device__ float g_bz[CC];                     // 0.5 * (bc_z@Wl_z + bl_z)
__device__ float g_bh[CC];
__device__ float g_ph[TT];                     // 0.5 * softmax(attention)
__device__ __align__(16) ulonglong2 g_W1p[(CC / 4) * HIDN]; // W1 packed pairs
__device__ __align__(16) float g_W2t[OUTN * HIDN];          // W2 transposed [oo][k]
__device__ float g_h[NN * CC];                 // fallback h buffer

// --------- K1: deg init + zero y + W1/W2 pack + composite weights + softmax
__global__ void k_init_w(const float* __restrict__ Wc_z, const float* __restrict__ bc_z,
                         const float* __restrict__ Wl_z, const float* __restrict__ bl_z,
                         const float* __restrict__ Wc_h, const float* __restrict__ bc_h,
                         const float* __restrict__ Wl_h, const float* __restrict__ bl_h,
                         const float* __restrict__ att, const float* __restrict__ W1,
                         const float* __restrict__ W2) {
    if (blockIdx.x == 0) {
        int t = threadIdx.x;              // 0..511
        int g = t >> 8;                   // 0 = z, 1 = h
        int c = t & (CC - 1);
        const float* Wc = g ? Wc_h : Wc_z;
        const float* bc = g ? bc_h : bc_z;
        const float* Wl = g ? Wl_h : Wl_z;
        const float* bl = g ? bl_h : bl_z;
        float a0 = 0, a1 = 0, a2 = 0, a3 = 0, ab = 0;
        for (int k = 0; k < CC; k++) {
            float wl = Wl[k * CC + c];    // first C rows of [2C, C]
            a0 += Wc[0 * CC + k] * wl;
            a1 += Wc[1 * CC + k] * wl;
            a2 += Wc[2 * CC + k] * wl;
            a3 += Wc[3 * CC + k] * wl;
            ab += bc[k] * wl;
        }
        float s = g ? 1.0f : 0.5f;        // fold tanh half-angle into z side
        float* M = g ? g_Mh : g_Mz;
        float* B = g ? g_bh : g_bz;
        M[0 * CC + c] = a0 * s;
        M[1 * CC + c] = a1 * s;
        M[2 * CC + c] = a2 * s;
        M[3 * CC + c] = a3 * s;
        B[c] = (ab + bl[c]) * s;
        if (t == 0) {                     // 0.5 * softmax(attention)
            float m = -1e30f;
            for (int k = 0; k < TT; k++) m = fmaxf(m, att[k]);
            float sum = 0.0f, e[TT];
            for (int k = 0; k < TT; k++) { e[k] = __expf(att[k] - m); sum += e[k]; }
            float inv = 0.5f / sum;
            for (int k = 0; k < TT; k++) g_ph[k] = e[k] * inv;
        }
    } else {
        int i = (blockIdx.x - 1) * blockDim.x + threadIdx.x;
        if (i < NREG * NN) g_deg[i] = 1.0f;            // +1 from self-loop
        if (i < NN * TT)                               // zero message buffer
            reinterpret_cast<float4*>(g_y)[i] = make_float4(0.f, 0.f, 0.f, 0.f);
        if (i < (CC / 4) * HIDN) {                     // pack W1 -> pair layout
            int k4 = i >> 7, hid = i & (HIDN - 1);
            float w0 = W1[(k4 * 4 + 0) * HIDN + hid];
            float w1 = W1[(k4 * 4 + 1) * HIDN + hid];
            float w2 = W1[(k4 * 4 + 2) * HIDN + hid];
            float w3 = W1[(k4 * 4 + 3) * HIDN + hid];
            ulonglong2 p; p.x = pack2(w0, w1); p.y = pack2(w2, w3);
            g_W1p[i] = p;
        }
        if (i < OUTN * HIDN) {                         // W2 transposed [oo][k]
            int oo = i >> 7, k = i & (HIDN - 1);
            g_W2t[i] = W2[k * OUTN + oo];
        }
    }
}

// ------------------------------------------------------------- K2: deg scatter
__global__ void k_deg(RegPtrs rp) {
    int i = blockIdx.x * blockDim.x + threadIdx.x;
    if (i >= NREG * ERN) return;
    int r = i / ERN;
    int e = i - r * ERN;
    int dst = rp.ei[r][ERN + e];
    atomicAdd(&g_deg[r * NN + dst], rp.ew[r][e]);
}

// ------------------- K3: message scatter with vector red: y[dst] += coef*x[src]
__global__ void __launch_bounds__(256) k_msg(const float* __restrict__ x, RegPtrs rp) {
    int i = blockIdx.x * blockDim.x + threadIdx.x;   // one edge
    if (i >= NREG * ERN) return;
    int r = i / ERN;
    int e = i - r * ERN;
    int src = rp.ei[r][e];
    int dst = rp.ei[r][ERN + e];
    float w = rp.ew[r][e];
    float coef = rsqrtf(g_deg[r * NN + src]) * w * rsqrtf(g_deg[r * NN + dst]);
    const float4* xs = reinterpret_cast<const float4*>(x) + src * TT;
    float4* yp = reinterpret_cast<float4*>(g_y + dst * FT);
    float4 v[TT];
#pragma unroll
    for (int ch = 0; ch < TT; ch++) v[ch] = xs[ch];
#pragma unroll
    for (int ch = 0; ch < TT; ch++)
        red4(yp + ch, coef * v[ch].x, coef * v[ch].y, coef * v[ch].z, coef * v[ch].w);
}

// ------------------- K4: gate: 8 nodes per block, 256 channels
// h[n,c] = sum_t (0.5 p_t)(1 - tanh(az/2)) tanh(ah)
__global__ void __launch_bounds__(256) k_gate(const float* __restrict__ x,
                                              float* __restrict__ hout) {
    __shared__ __align__(16) u64 ysp[GNB * 24];       // [nn][tp*4+f] t-pairs
    __shared__ float Ssh[GNB];

    int tid = threadIdx.x;
    int node0 = blockIdx.x * GNB;

    if (tid < GNB) {                                  // self-loop coefficients
        int n = node0 + tid;
        float S = 0.0f;
#pragma unroll
        for (int r = 0; r < NREG; r++) {
            float d = rsqrtf(g_deg[r * NN + n]);
            S += d * d;
        }
        Ssh[tid] = S;
    }
    __syncthreads();

    // build ysp: v = msg + S*x -> t-pair layout (8*48 = 384 elements)
    float* yspf = reinterpret_cast<float*>(ysp);
    for (int i = tid; i < GNB * FT; i += 256) {
        int nn = i / FT, j = i - nn * FT;             // j = f*12 + t
        int f = j / TT, t = j - f * TT;
        float v = g_y[(node0 + nn) * FT + j] + Ssh[nn] * x[(node0 + nn) * FT + j];
        yspf[(nn * 24 + (t >> 1) * 4 + f) * 2 + (t & 1)] = v;
    }
    __syncthreads();

    int c = tid;
    u64 mz0 = pack2(g_Mz[0 * CC + c], g_Mz[0 * CC + c]);
    u64 mz1 = pack2(g_Mz[1 * CC + c], g_Mz[1 * CC + c]);
    u64 mz2 = pack2(g_Mz[2 * CC + c], g_Mz[2 * CC + c]);
    u64 mz3 = pack2(g_Mz[3 * CC + c], g_Mz[3 * CC + c]);
    u64 mh0 = pack2(g_Mh[0 * CC + c], g_Mh[0 * CC + c]);
    u64 mh1 = pack2(g_Mh[1 * CC + c], g_Mh[1 * CC + c]);
    u64 mh2 = pack2(g_Mh[2 * CC + c], g_Mh[2 * CC + c]);
    u64 mh3 = pack2(g_Mh[3 * CC + c], g_Mh[3 * CC + c]);
    u64 bzp = pack2(g_bz[c], g_bz[c]);
    u64 bhp = pack2(g_bh[c], g_bh[c]);
    float phr[TT];
#pragma unroll
    for (int t = 0; t < TT; t++) phr[t] = g_ph[t];

#pragma unroll 2
    for (int nn = 0; nn < GNB; nn++) {
        float h0 = 0.0f, h1 = 0.0f;
#pragma unroll
        for (int tp = 0; tp < 6; tp++) {
            ulonglong2 ya = *reinterpret_cast<const ulonglong2*>(&ysp[nn * 24 + tp * 4]);
            ulonglong2 yb = *reinterpret_cast<const ulonglong2*>(&ysp[nn * 24 + tp * 4 + 2]);
            u64 az = ffma2(ya.x, mz0, bzp);
            u64 ah = ffma2(ya.x, mh0, bhp);
            az = ffma2(ya.y, mz1, az);
            ah = ffma2(ya.y, mh1, ah);
            az = ffma2(yb.x, mz2, az);
            ah = ffma2(yb.x, mh2, ah);
            az = ffma2(yb.y, mz3, az);
            ah = ffma2(yb.y, mh3, ah);
            float az0, az1, ah0, ah1;
            unpack2(az, az0, az1);
            unpack2(ah, ah0, ah1);
            float tz0 = tanh_fast(az0), th0 = tanh_fast(ah0);
            float tz1 = tanh_fast(az1), th1 = tanh_fast(ah1);
            float q0 = fmaf(-tz0, th0, th0);          // (1 - tz) * th
            float q1 = fmaf(-tz1, th1, th1);
            h0 = fmaf(phr[2 * tp],     q0, h0);
            h1 = fmaf(phr[2 * tp + 1], q1, h1);
        }
        hout[(size_t)(node0 + nn) * CC + c] = h0 + h1;
    }
}

// ------------------- K5: MLP y = relu(relu(h)@W1+b1)@W2+b2 (32 nodes/block)
__global__ void __launch_bounds__(256) k_mlp(const float* __restrict__ h_src,
                                             const float* __restrict__ b1,
                                             const float* __restrict__ b2,
                                             float* __restrict__ yout) {
    __shared__ __align__(16) float hs[MNB * CC];     // 32 KB (aliased by s1)
    float* s1 = hs;                                  // layer-1 acts alias

    int tid = threadIdx.x;
    int node0 = blockIdx.x * MNB;

    // stage relu(h) tile (2048 float4)
    for (int i = tid; i < MNB * CC / 4; i += 256) {
        float4 v = reinterpret_cast<const float4*>(h_src + (size_t)node0 * CC)[i];
        v.x = fmaxf(v.x, 0.0f); v.y = fmaxf(v.y, 0.0f);
        v.z = fmaxf(v.z, 0.0f); v.w = fmaxf(v.w, 0.0f);
        reinterpret_cast<float4*>(hs)[i] = v;
    }
    __syncthreads();

    // ---- layer 1: [32,256] @ [256,128]; 2 hid x 8 nodes per thread
    int ng   = tid >> 6;                              // node group 0..3 (8 nodes)
    int hidp = tid & 63;                              // hid base; also hid+64
    const float* hsg = hs + ng * 8 * CC;
    float biasA = b1[hidp], biasB = b1[hidp + 64];

    u64 accA[8], accB[8];
#pragma unroll
    for (int nn = 0; nn < 8; nn++) { accA[nn] = 0ull; accB[nn] = 0ull; }

#pragma unroll 2
    for (int k4 = 0; k4 < CC / 4; k4++) {
        ulonglong2 wa = g_W1p[k4 * HIDN + hidp];
        ulonglong2 wb = g_W1p[k4 * HIDN + hidp + 64];
#pragma unroll
        for (int nn = 0; nn < 8; nn++) {
            ulonglong2 hv = *reinterpret_cast<const ulonglong2*>(hsg + nn * CC + k4 * 4);
            accA[nn] = ffma2(hv.x, wa.x, accA[nn]);
            accA[nn] = ffma2(hv.y, wa.y, accA[nn]);
            accB[nn] = ffma2(hv.x, wb.x, accB[nn]);
            accB[nn] = ffma2(hv.y, wb.y, accB[nn]);
        }
    }

    float resA[8], resB[8];
#pragma unroll
    for (int nn = 0; nn < 8; nn++) {
        float lo, hi;
        unpack2(accA[nn], lo, hi);
        resA[nn] = fmaxf(lo + hi + biasA, 0.0f);
        unpack2(accB[nn], lo, hi);
        resB[nn] = fmaxf(lo + hi + biasB, 0.0f);
    }
    __syncthreads();                                  // hs reads done before alias
#pragma unroll
    for (int nn = 0; nn < 8; nn++) {
        s1[(ng * 8 + nn) * HIDN + hidp]      = resA[nn];
        s1[(ng * 8 + nn) * HIDN + hidp + 64] = resB[nn];
    }
    __syncthreads();

    // ---- layer 2: 32 nodes x 12 outputs, float4 over k (W2t from L1/L2)
    for (int o = tid; o < MNB * OUTN; o += 256) {
        int node = o / OUTN;
        int oo   = o - node * OUTN;
        float a = b2[oo];
#pragma unroll
        for (int k4 = 0; k4 < HIDN / 4; k4++) {
            float4 sv = *reinterpret_cast<const float4*>(s1 + node * HIDN + k4 * 4);
            float4 wv = *reinterpret_cast<const float4*>(g_W2t + oo * HIDN + k4 * 4);
            a = fmaf(sv.x, wv.x, a);
            a = fmaf(sv.y, wv.y, a);
            a = fmaf(sv.z, wv.z, a);
            a = fmaf(sv.w, wv.w, a);
        }
        yout[(node0 + node) * OUTN + oo] = a;
    }
}

// ================================================================== host
extern "C" void kernel_launch(void* const* d_in, const int* in_sizes, int n_in,
                              void* d_out, int out_size) {
    const float* x = (const float*)d_in[0];
    RegPtrs rp;
    for (int r = 0; r < NREG; r++) {
        rp.ei[r] = (const int*)d_in[2 + r];     // IA,KS,KY,OH,WI edge_index
        rp.ew[r] = (const float*)d_in[7 + r];   // matching edge_attr
    }
    const float* Wc_z = (const float*)d_in[12];
    const float* bc_z = (const float*)d_in[13];
    const float* Wl_z = (const float*)d_in[14];
    const float* bl_z = (const float*)d_in[15];
    const float* Wc_h = (const float*)d_in[20];
    const float* bc_h = (const float*)d_in[21];
    const float* Wl_h = (const float*)d_in[22];
    const float* bl_h = (const float*)d_in[23];
    const float* att  = (const float*)d_in[24];
    const float* W1   = (const float*)d_in[25];
    const float* b1   = (const float*)d_in[26];
    const float* W2   = (const float*)d_in[27];
    const float* b2   = (const float*)d_in[28];

    float* out  = (float*)d_out;
    float* ydst = nullptr;
    float* hdst = nullptr;
    if (out_size >= NN * OUTN + NN * CC) { ydst = out; hdst = out + NN * OUTN; }
    else if (out_size >= NN * CC)        { hdst = out; }
    else                                 { ydst = out; }

    float* hbuf = hdst;
    if (!hbuf) {
        void* p = nullptr;
        cudaGetSymbolAddress(&p, g_h);
        hbuf = (float*)p;
    }

    k_init_w<<<1 + (NN * TT + 511) / 512, 512>>>(Wc_z, bc_z, Wl_z, bl_z,
                                                 Wc_h, bc_h, Wl_h, bl_h, att, W1, W2);
    k_deg<<<(NREG * ERN + 255) / 256, 256>>>(rp);
    k_msg<<<(NREG * ERN + 255) / 256, 256>>>(x, rp);
    k_gate<<<NN / GNB, 256>>>(x, hbuf);
    if (ydst) k_mlp<<<NN / MNB, 256>>>(hbuf, b1, b2, ydst);
}

// round 14
// speedup vs baseline: 1.6913x; 1.6913x over previous
#include <cuda_runtime.h>

#define NN   20000
#define FF   4
#define TT   12
#define CC   256
#define HIDN 128
#define OUTN 12
#define ERN  30000
#define NREG 5
#define FT   48   // F*T floats per node
#define NB   16   // nodes per fused block
#define EPT  4    // threads per edge in k_msg

typedef unsigned long long u64;

struct RegPtrs { const int* ei[NREG]; const float* ew[NREG]; };

// ---------------------------------------------------------------- helpers
__device__ __forceinline__ u64 pack2(float lo, float hi) {
    u64 r; asm("mov.b64 %0,{%1,%2};" : "=l"(r) : "f"(lo), "f"(hi)); return r;
}
__device__ __forceinline__ void unpack2(u64 v, float& lo, float& hi) {
    asm("mov.b64 {%0,%1},%2;" : "=f"(lo), "=f"(hi) : "l"(v));
}
__device__ __forceinline__ u64 ffma2(u64 a, u64 b, u64 c) {
    u64 d; asm("fma.rn.f32x2 %0,%1,%2,%3;" : "=l"(d) : "l"(a), "l"(b), "l"(c)); return d;
}
__device__ __forceinline__ float tanh_fast(float x) {
    float r; asm("tanh.approx.f32 %0,%1;" : "=f"(r) : "f"(x)); return r;
}
__device__ __forceinline__ void red4(float4* p, float a, float b, float c, float d) {
    asm volatile("red.global.add.v4.f32 [%0], {%1,%2,%3,%4};"
                 :: "l"(p), "f"(a), "f"(b), "f"(c), "f"(d) : "memory");
}

// ---------------------------------------------------------------- scratch
__device__ float g_deg[NREG * NN];
__device__ __align__(16) float g_y[NN * FT];   // message accumulator [N, F, T]
__device__ float g_Mz[FF * CC];                // 0.5 * Wc_z@Wl_z[:C]
__device__ float g_Mh[FF * CC];                // Wc_h@Wl_h[:C]
__device__ float g_bz[CC];                     // 0.5 * (bc_z@Wl_z + bl_z)
__device__ float g_bh[CC];
__device__ float g_ph[TT];                     // 0.5 * softmax(attention)
__device__ __align__(16) ulonglong2 g_W1p[(CC / 4) * HIDN]; // W1 packed pairs
__device__ float g_h[NN * CC];                 // fallback h buffer

// --------- K1: deg init + zero y + W1 pack + composite weights + softmax
__global__ void k_init_w(const float* __restrict__ Wc_z, const float* __restrict__ bc_z,
                         const float* __restrict__ Wl_z, const float* __restrict__ bl_z,
                         const float* __restrict__ Wc_h, const float* __restrict__ bc_h,
                         const float* __restrict__ Wl_h, const float* __restrict__ bl_h,
                         const float* __restrict__ att, const float* __restrict__ W1) {
    if (blockIdx.x == 0) {
        int t = threadIdx.x;              // 0..511
        int g = t >> 8;                   // 0 = z, 1 = h
        int c = t & (CC - 1);
        const float* Wc = g ? Wc_h : Wc_z;
        const float* bc = g ? bc_h : bc_z;
        const float* Wl = g ? Wl_h : Wl_z;
        const float* bl = g ? bl_h : bl_z;
        float a0 = 0, a1 = 0, a2 = 0, a3 = 0, ab = 0;
        for (int k = 0; k < CC; k++) {
            float wl = Wl[k * CC + c];    // first C rows of [2C, C]
            a0 += Wc[0 * CC + k] * wl;
            a1 += Wc[1 * CC + k] * wl;
            a2 += Wc[2 * CC + k] * wl;
            a3 += Wc[3 * CC + k] * wl;
            ab += bc[k] * wl;
        }
        float s = g ? 1.0f : 0.5f;        // fold tanh half-angle into z side
        float* M = g ? g_Mh : g_Mz;
        float* B = g ? g_bh : g_bz;
        M[0 * CC + c] = a0 * s;
        M[1 * CC + c] = a1 * s;
        M[2 * CC + c] = a2 * s;
        M[3 * CC + c] = a3 * s;
        B[c] = (ab + bl[c]) * s;
        if (t == 0) {                     // 0.5 * softmax(attention)
            float m = -1e30f;
            for (int k = 0; k < TT; k++) m = fmaxf(m, att[k]);
            float sum = 0.0f, e[TT];
            for (int k = 0; k < TT; k++) { e[k] = __expf(att[k] - m); sum += e[k]; }
            float inv = 0.5f / sum;
            for (int k = 0; k < TT; k++) g_ph[k] = e[k] * inv;
        }
    } else {
        int i = (blockIdx.x - 1) * blockDim.x + threadIdx.x;
        if (i < NREG * NN) g_deg[i] = 1.0f;            // +1 from self-loop
        if (i < NN * TT)                               // zero message buffer
            reinterpret_cast<float4*>(g_y)[i] = make_float4(0.f, 0.f, 0.f, 0.f);
        if (i < (CC / 4) * HIDN) {                     // pack W1 -> pair layout
            int k4 = i >> 7, hid = i & (HIDN - 1);
            float w0 = W1[(k4 * 4 + 0) * HIDN + hid];
            float w1 = W1[(k4 * 4 + 1) * HIDN + hid];
            float w2 = W1[(k4 * 4 + 2) * HIDN + hid];
            float w3 = W1[(k4 * 4 + 3) * HIDN + hid];
            ulonglong2 p; p.x = pack2(w0, w1); p.y = pack2(w2, w3);
            g_W1p[i] = p;
        }
    }
}

// ------------------------------------------------------------- K2: deg scatter
__global__ void k_deg(RegPtrs rp) {
    int i = blockIdx.x * blockDim.x + threadIdx.x;
    if (i >= NREG * ERN) return;
    int r = i / ERN;
    int e = i - r * ERN;
    int dst = rp.ei[r][ERN + e];
    atomicAdd(&g_deg[r * NN + dst], rp.ew[r][e]);
}

// ----------- K3: message scatter, 4 threads per edge (3 red4 chunks each)
__global__ void __launch_bounds__(256) k_msg(const float* __restrict__ x, RegPtrs rp) {
    int i = blockIdx.x * blockDim.x + threadIdx.x;   // (edge, quarter)
    if (i >= NREG * ERN * EPT) return;
    int sub = i & (EPT - 1);
    int eg  = i >> 2;                                 // edge global index
    int r   = eg / ERN;
    int e   = eg - r * ERN;
    int src = rp.ei[r][e];
    int dst = rp.ei[r][ERN + e];
    float w = rp.ew[r][e];
    float coef = rsqrtf(g_deg[r * NN + src]) * w * rsqrtf(g_deg[r * NN + dst]);
    const float4* xs = reinterpret_cast<const float4*>(x) + src * TT + sub * 3;
    float4* yp = reinterpret_cast<float4*>(g_y + dst * FT) + sub * 3;
    float4 v0 = xs[0], v1 = xs[1], v2 = xs[2];
    red4(yp + 0, coef * v0.x, coef * v0.y, coef * v0.z, coef * v0.w);
    red4(yp + 1, coef * v1.x, coef * v1.y, coef * v1.z, coef * v1.w);
    red4(yp + 2, coef * v2.x, coef * v2.y, coef * v2.z, coef * v2.w);
}

// ------------------- K4: fused self-loop + gates + attention pooling + MLP
// EXACT R9 golden config: 16 nodes, no reg cap, W2 staged in smem.
__global__ void __launch_bounds__(256) k_fused(const float* __restrict__ x,
                                               const float* __restrict__ b1,
                                               const float* __restrict__ W2,
                                               const float* __restrict__ b2,
                                               float* __restrict__ hout,
                                               float* __restrict__ yout) {
    // ysp: [nn][tp][f] u64 pairs (y_f(2tp), y_f(2tp+1)) : 16*6*4*8 = 3072 B
    __shared__ __align__(16) u64   ysp[NB * 6 * FF];
    __shared__ __align__(16) float hs [NB * CC];     // 16 KB (aliased by s1)
    __shared__ float w2t[OUTN * HIDN];               // 6 KB transposed W2
    __shared__ float Ssh[NB];

    float* s1 = hs;                                  // layer-1 acts alias

    int tid = threadIdx.x;
    int node0 = blockIdx.x * NB;

    if (tid < NB) {                                  // self-loop coefficient S
        int n = node0 + tid;
        float S = 0.0f;
#pragma unroll
        for (int r = 0; r < NREG; r++) {
            float d = rsqrtf(g_deg[r * NN + n]);
            S += d * d;
        }
        Ssh[tid] = S;
    }
    // stage W2 transposed: w2t[oo*HIDN + k]
    for (int i = tid; i < HIDN * OUTN; i += 256) {
        int oo = i >> 7, k = i & (HIDN - 1);
        w2t[i] = W2[k * OUTN + oo];
    }
    __syncthreads();

    // build ysp: v = msg + S*x, scattered into t-pair layout
    float* yspf = reinterpret_cast<float*>(ysp);
    for (int i = tid; i < NB * FT; i += 256) {
        int nn = i / FT, j = i - nn * FT;            // j = f*12 + t
        int f = j / TT, t = j - f * TT;
        float v = g_y[(node0 + nn) * FT + j] + Ssh[nn] * x[(node0 + nn) * FT + j];
        yspf[(nn * 24 + (t >> 1) * 4 + f) * 2 + (t & 1)] = v;
    }
    __syncthreads();

    // ---- gate: h[nn][c] = sum_t (0.5 p_t)(1 - tanh(az/2)) tanh(ah)
    int c = tid;
    u64 mz0 = pack2(g_Mz[0 * CC + c], g_Mz[0 * CC + c]);
    u64 mz1 = pack2(g_Mz[1 * CC + c], g_Mz[1 * CC + c]);
    u64 mz2 = pack2(g_Mz[2 * CC + c], g_Mz[2 * CC + c]);
    u64 mz3 = pack2(g_Mz[3 * CC + c], g_Mz[3 * CC + c]);
    u64 mh0 = pack2(g_Mh[0 * CC + c], g_Mh[0 * CC + c]);
    u64 mh1 = pack2(g_Mh[1 * CC + c], g_Mh[1 * CC + c]);
    u64 mh2 = pack2(g_Mh[2 * CC + c], g_Mh[2 * CC + c]);
    u64 mh3 = pack2(g_Mh[3 * CC + c], g_Mh[3 * CC + c]);
    u64 bzp = pack2(g_bz[c], g_bz[c]);
    u64 bhp = pack2(g_bh[c], g_bh[c]);
    float phr[TT];
#pragma unroll
    for (int t = 0; t < TT; t++) phr[t] = g_ph[t];

#pragma unroll 2
    for (int nn = 0; nn < NB; nn++) {
        float h0 = 0.0f, h1 = 0.0f;                   // scalar pooling accums
#pragma unroll
        for (int tp = 0; tp < 6; tp++) {
            ulonglong2 ya = *reinterpret_cast<const ulonglong2*>(&ysp[nn * 24 + tp * 4]);
            ulonglong2 yb = *reinterpret_cast<const ulonglong2*>(&ysp[nn * 24 + tp * 4 + 2]);
            u64 az = ffma2(ya.x, mz0, bzp);
            u64 ah = ffma2(ya.x, mh0, bhp);
            az = ffma2(ya.y, mz1, az);
            ah = ffma2(ya.y, mh1, ah);
            az = ffma2(yb.x, mz2, az);
            ah = ffma2(yb.x, mh2, ah);
            az = ffma2(yb.y, mz3, az);
            ah = ffma2(yb.y, mh3, ah);
            float az0, az1, ah0, ah1;
            unpack2(az, az0, az1);
            unpack2(ah, ah0, ah1);
            float tz0 = tanh_fast(az0), th0 = tanh_fast(ah0);
            float tz1 = tanh_fast(az1), th1 = tanh_fast(ah1);
            float q0 = fmaf(-tz0, th0, th0);          // (1 - tz) * th
            float q1 = fmaf(-tz1, th1, th1);
            h0 = fmaf(phr[2 * tp],     q0, h0);
            h1 = fmaf(phr[2 * tp + 1], q1, h1);
        }
        float h = h0 + h1;
        hout[(size_t)(node0 + nn) * CC + c] = h;      // raw h output
        hs[nn * CC + c] = fmaxf(h, 0.0f);             // relu'd for MLP
    }

    if (!yout) return;
    __syncthreads();                                  // hs complete

    // ---- MLP layer 1: [16,256] @ [256,128]; 2 hid x 4 nodes per thread
    int ng   = tid >> 6;                              // node group 0..3 (4 nodes)
    int hidp = tid & 63;                              // hid base; also hid+64
    const float* hsg = hs + ng * 4 * CC;

    u64 accA[4], accB[4];
#pragma unroll
    for (int nn = 0; nn < 4; nn++) { accA[nn] = 0ull; accB[nn] = 0ull; }

#pragma unroll 2
    for (int k4 = 0; k4 < CC / 4; k4++) {
        ulonglong2 wa = g_W1p[k4 * HIDN + hidp];
        ulonglong2 wb = g_W1p[k4 * HIDN + hidp + 64];
#pragma unroll
        for (int nn = 0; nn < 4; nn++) {
            ulonglong2 hv = *reinterpret_cast<const ulonglong2*>(hsg + nn * CC + k4 * 4);
            accA[nn] = ffma2(hv.x, wa.x, accA[nn]);
            accA[nn] = ffma2(hv.y, wa.y, accA[nn]);
            accB[nn] = ffma2(hv.x, wb.x, accB[nn]);
            accB[nn] = ffma2(hv.y, wb.y, accB[nn]);
        }
    }

    float biasA = b1[hidp], biasB = b1[hidp + 64];
    float resA[4], resB[4];
#pragma unroll
    for (int nn = 0; nn < 4; nn++) {
        float lo, hi;
        unpack2(accA[nn], lo, hi);
        resA[nn] = fmaxf(lo + hi + biasA, 0.0f);
        unpack2(accB[nn], lo, hi);
        resB[nn] = fmaxf(lo + hi + biasB, 0.0f);
    }
    __syncthreads();                                  // hs reads done before alias
#pragma unroll
    for (int nn = 0; nn < 4; nn++) {
        s1[(ng * 4 + nn) * HIDN + hidp]      = resA[nn];
        s1[(ng * 4 + nn) * HIDN + hidp + 64] = resB[nn];
    }
    __syncthreads();

    // ---- MLP layer 2: 16 nodes x 12 outputs, float4 over k
    if (tid < NB * OUTN) {
        int node = tid / OUTN;
        int oo   = tid - node * OUTN;
        float a = b2[oo];
#pragma unroll
        for (int k4 = 0; k4 < HIDN / 4; k4++) {
            float4 sv = *reinterpret_cast<const float4*>(s1 + node * HIDN + k4 * 4);
            float4 wv = *reinterpret_cast<const float4*>(w2t + oo * HIDN + k4 * 4);
            a = fmaf(sv.x, wv.x, a);
            a = fmaf(sv.y, wv.y, a);
            a = fmaf(sv.z, wv.z, a);
            a = fmaf(sv.w, wv.w, a);
        }
        yout[(node0 + node) * OUTN + oo] = a;
    }
}

// ================================================================== host
extern "C" void kernel_launch(void* const* d_in, const int* in_sizes, int n_in,
                              void* d_out, int out_size) {
    const float* x = (const float*)d_in[0];
    RegPtrs rp;
    for (int r = 0; r < NREG; r++) {
        rp.ei[r] = (const int*)d_in[2 + r];     // IA,KS,KY,OH,WI edge_index
        rp.ew[r] = (const float*)d_in[7 + r];   // matching edge_attr
    }
    const float* Wc_z = (const float*)d_in[12];
    const float* bc_z = (const float*)d_in[13];
    const float* Wl_z = (const float*)d_in[14];
    const float* bl_z = (const float*)d_in[15];
    const float* Wc_h = (const float*)d_in[20];
    const float* bc_h = (const float*)d_in[21];
    const float* Wl_h = (const float*)d_in[22];
    const float* bl_h = (const float*)d_in[23];
    const float* att  = (const float*)d_in[24];
    const float* W1   = (const float*)d_in[25];
    const float* b1   = (const float*)d_in[26];
    const float* W2   = (const float*)d_in[27];
    const float* b2   = (const float*)d_in[28];

    float* out  = (float*)d_out;
    float* ydst = nullptr;
    float* hdst = nullptr;
    if (out_size >= NN * OUTN + NN * CC) { ydst = out; hdst = out + NN * OUTN; }
    else if (out_size >= NN * CC)        { hdst = out; }
    else                                 { ydst = out; }

    float* hbuf = hdst;
    if (!hbuf) {
        void* p = nullptr;
        cudaGetSymbolAddress(&p, g_h);
        hbuf = (float*)p;
    }

    k_init_w<<<1 + (NN * TT + 511) / 512, 512>>>(Wc_z, bc_z, Wl_z, bl_z,
                                                 Wc_h, bc_h, Wl_h, bl_h, att, W1);
    k_deg<<<(NREG * ERN + 255) / 256, 256>>>(rp);
    k_msg<<<(NREG * ERN * EPT + 255) / 256, 256>>>(x, rp);
    k_fused<<<NN / NB, 256>>>(x, b1, W2, b2, hbuf, ydst);
}

// round 15
// speedup vs baseline: 1.7460x; 1.0323x over previous
#include <cuda_runtime.h>

#define NN   20000
#define FF   4
#define TT   12
#define CC   256
#define HIDN 128
#define OUTN 12
#define ERN  30000
#define NREG 5
#define FT   48   // F*T floats per node
#define NB   16   // nodes per fused block

typedef unsigned long long u64;

struct RegPtrs { const int* ei[NREG]; const float* ew[NREG]; };

// ---------------------------------------------------------------- helpers
__device__ __forceinline__ u64 pack2(float lo, float hi) {
    u64 r; asm("mov.b64 %0,{%1,%2};" : "=l"(r) : "f"(lo), "f"(hi)); return r;
}
__device__ __forceinline__ void unpack2(u64 v, float& lo, float& hi) {
    asm("mov.b64 {%0,%1},%2;" : "=f"(lo), "=f"(hi) : "l"(v));
}
__device__ __forceinline__ u64 ffma2(u64 a, u64 b, u64 c) {
    u64 d; asm("fma.rn.f32x2 %0,%1,%2,%3;" : "=l"(d) : "l"(a), "l"(b), "l"(c)); return d;
}
__device__ __forceinline__ float tanh_fast(float x) {
    float r; asm("tanh.approx.f32 %0,%1;" : "=f"(r) : "f"(x)); return r;
}
__device__ __forceinline__ void red4(float4* p, float a, float b, float c, float d) {
    asm volatile("red.global.add.v4.f32 [%0], {%1,%2,%3,%4};"
                 :: "l"(p), "f"(a), "f"(b), "f"(c), "f"(d) : "memory");
}

// ---------------------------------------------------------------- scratch
__device__ float g_deg[NREG * NN];
__device__ __align__(16) float g_y[NN * FT];   // message accumulator [N, F, T]
__device__ float g_Mz[FF * CC];                // 0.5 * Wc_z@Wl_z[:C]
__device__ float g_Mh[FF * CC];                // Wc_h@Wl_h[:C]
__device__ float g_bz[CC];                     // 0.5 * (bc_z@Wl_z + bl_z)
__device__ float g_bh[CC];
__device__ float g_ph[TT];                     // 0.5 * softmax(attention)
__device__ __align__(16) ulonglong2 g_W1p[(CC / 4) * HIDN]; // W1 packed pairs
__device__ float g_h[NN * CC];                 // fallback h buffer

// --------- K1: deg init + zero y + W1 pack + composite weights + softmax
// Blocks 0,1: composite weights for g=z,h with 2-way k-split per (c).
// Blocks 2..: init g_deg / zero g_y / pack W1.
__global__ void k_init_w(const float* __restrict__ Wc_z, const float* __restrict__ bc_z,
                         const float* __restrict__ Wl_z, const float* __restrict__ bl_z,
                         const float* __restrict__ Wc_h, const float* __restrict__ bc_h,
                         const float* __restrict__ Wl_h, const float* __restrict__ bl_h,
                         const float* __restrict__ att, const float* __restrict__ W1) {
    if (blockIdx.x < 2) {
        __shared__ float part[512 * 5];       // partial sums [thread][5]
        int g = blockIdx.x;                   // 0 = z, 1 = h
        int t = threadIdx.x;                  // 0..511
        int kh = t >> 8;                      // k half
        int c = t & (CC - 1);
        const float* Wc = g ? Wc_h : Wc_z;
        const float* bc = g ? bc_h : bc_z;
        const float* Wl = g ? Wl_h : Wl_z;
        const float* bl = g ? bl_h : bl_z;
        float a0 = 0, a1 = 0, a2 = 0, a3 = 0, ab = 0;
        for (int k = kh * 128; k < (kh + 1) * 128; k++) {
            float wl = Wl[k * CC + c];        // first C rows of [2C, C]
            a0 += Wc[0 * CC + k] * wl;
            a1 += Wc[1 * CC + k] * wl;
            a2 += Wc[2 * CC + k] * wl;
            a3 += Wc[3 * CC + k] * wl;
            ab += bc[k] * wl;
        }
        part[t * 5 + 0] = a0; part[t * 5 + 1] = a1; part[t * 5 + 2] = a2;
        part[t * 5 + 3] = a3; part[t * 5 + 4] = ab;
        __syncthreads();
        if (kh == 0) {                        // threads 0..255 combine halves
            float s = g ? 1.0f : 0.5f;        // fold tanh half-angle into z side
            float* M = g ? g_Mh : g_Mz;
            float* B = g ? g_bh : g_bz;
            int o = (256 + c) * 5;            // partner thread's partials
            M[0 * CC + c] = (part[c * 5 + 0] + part[o + 0]) * s;
            M[1 * CC + c] = (part[c * 5 + 1] + part[o + 1]) * s;
            M[2 * CC + c] = (part[c * 5 + 2] + part[o + 2]) * s;
            M[3 * CC + c] = (part[c * 5 + 3] + part[o + 3]) * s;
            B[c] = ((part[c * 5 + 4] + part[o + 4]) + bl[c]) * s;
        }
        if (g == 0 && t == 0) {               // 0.5 * softmax(attention)
            float m = -1e30f;
            for (int k = 0; k < TT; k++) m = fmaxf(m, att[k]);
            float sum = 0.0f, e[TT];
            for (int k = 0; k < TT; k++) { e[k] = __expf(att[k] - m); sum += e[k]; }
            float inv = 0.5f / sum;
            for (int k = 0; k < TT; k++) g_ph[k] = e[k] * inv;
        }
    } else {
        int i = (blockIdx.x - 2) * blockDim.x + threadIdx.x;
        if (i < NREG * NN) g_deg[i] = 1.0f;            // +1 from self-loop
        if (i < NN * TT)                               // zero message buffer
            reinterpret_cast<float4*>(g_y)[i] = make_float4(0.f, 0.f, 0.f, 0.f);
        if (i < (CC / 4) * HIDN) {                     // pack W1 -> pair layout
            int k4 = i >> 7, hid = i & (HIDN - 1);
            float w0 = W1[(k4 * 4 + 0) * HIDN + hid];
            float w1 = W1[(k4 * 4 + 1) * HIDN + hid];
            float w2 = W1[(k4 * 4 + 2) * HIDN + hid];
            float w3 = W1[(k4 * 4 + 3) * HIDN + hid];
            ulonglong2 p; p.x = pack2(w0, w1); p.y = pack2(w2, w3);
            g_W1p[i] = p;
        }
    }
}

// ------------------------------------------------------------- K2: deg scatter
__global__ void k_deg(RegPtrs rp) {
    int i = blockIdx.x * blockDim.x + threadIdx.x;
    if (i >= NREG * ERN) return;
    int r = i / ERN;
    int e = i - r * ERN;
    int dst = rp.ei[r][ERN + e];
    atomicAdd(&g_deg[r * NN + dst], rp.ew[r][e]);
}

// ------------------- K3: message scatter (R9 golden: 1 thread/edge, 12 red4)
__global__ void __launch_bounds__(256) k_msg(const float* __restrict__ x, RegPtrs rp) {
    int i = blockIdx.x * blockDim.x + threadIdx.x;   // one edge
    if (i >= NREG * ERN) return;
    int r = i / ERN;
    int e = i - r * ERN;
    int src = rp.ei[r][e];
    int dst = rp.ei[r][ERN + e];
    float w = rp.ew[r][e];
    float coef = rsqrtf(g_deg[r * NN + src]) * w * rsqrtf(g_deg[r * NN + dst]);
    const float4* xs = reinterpret_cast<const float4*>(x) + src * TT;
    float4* yp = reinterpret_cast<float4*>(g_y + dst * FT);
    float4 v[TT];
#pragma unroll
    for (int ch = 0; ch < TT; ch++) v[ch] = xs[ch];
#pragma unroll
    for (int ch = 0; ch < TT; ch++)
        red4(yp + ch, coef * v[ch].x, coef * v[ch].y, coef * v[ch].z, coef * v[ch].w);
}

// ------------------- K4: fused self-loop + gates + attention pooling + MLP
// R9 golden config: 16 nodes, no reg cap, W2 staged in smem, W1p from global.
__global__ void __launch_bounds__(256) k_fused(const float* __restrict__ x,
                                               const float* __restrict__ b1,
                                               const float* __restrict__ W2,
                                               const float* __restrict__ b2,
                                               float* __restrict__ hout,
                                               float* __restrict__ yout) {
    // ysp: [nn][tp][f] u64 pairs (y_f(2tp), y_f(2tp+1)) : 16*6*4*8 = 3072 B
    __shared__ __align__(16) u64   ysp[NB * 6 * FF];
    __shared__ __align__(16) float hs [NB * CC];     // 16 KB (aliased by s1)
    __shared__ float w2t[OUTN * HIDN];               // 6 KB transposed W2
    __shared__ float Ssh[NB];

    float* s1 = hs;                                  // layer-1 acts alias

    int tid = threadIdx.x;
    int node0 = blockIdx.x * NB;

    if (tid < NB) {                                  // self-loop coefficient S
        int n = node0 + tid;
        float S = 0.0f;
#pragma unroll
        for (int r = 0; r < NREG; r++) {
            float d = rsqrtf(g_deg[r * NN + n]);
            S += d * d;
        }
        Ssh[tid] = S;
    }
    // stage W2 transposed: w2t[oo*HIDN + k]
    for (int i = tid; i < HIDN * OUTN; i += 256) {
        int oo = i >> 7, k = i & (HIDN - 1);
        w2t[i] = W2[k * OUTN + oo];
    }
    __syncthreads();

    // build ysp: v = msg + S*x, scattered into t-pair layout
    float* yspf = reinterpret_cast<float*>(ysp);
    for (int i = tid; i < NB * FT; i += 256) {
        int nn = i / FT, j = i - nn * FT;            // j = f*12 + t
        int f = j / TT, t = j - f * TT;
        float v = g_y[(node0 + nn) * FT + j] + Ssh[nn] * x[(node0 + nn) * FT + j];
        yspf[(nn * 24 + (t >> 1) * 4 + f) * 2 + (t & 1)] = v;
    }
    __syncthreads();

    // ---- gate: h[nn][c] = sum_t (0.5 p_t)(1 - tanh(az/2)) tanh(ah)
    int c = tid;
    u64 mz0 = pack2(g_Mz[0 * CC + c], g_Mz[0 * CC + c]);
    u64 mz1 = pack2(g_Mz[1 * CC + c], g_Mz[1 * CC + c]);
    u64 mz2 = pack2(g_Mz[2 * CC + c], g_Mz[2 * CC + c]);
    u64 mz3 = pack2(g_Mz[3 * CC + c], g_Mz[3 * CC + c]);
    u64 mh0 = pack2(g_Mh[0 * CC + c], g_Mh[0 * CC + c]);
    u64 mh1 = pack2(g_Mh[1 * CC + c], g_Mh[1 * CC + c]);
    u64 mh2 = pack2(g_Mh[2 * CC + c], g_Mh[2 * CC + c]);
    u64 mh3 = pack2(g_Mh[3 * CC + c], g_Mh[3 * CC + c]);
    u64 bzp = pack2(g_bz[c], g_bz[c]);
    u64 bhp = pack2(g_bh[c], g_bh[c]);
    float phr[TT];
#pragma unroll
    for (int t = 0; t < TT; t++) phr[t] = g_ph[t];

#pragma unroll 2
    for (int nn = 0; nn < NB; nn++) {
        float h0 = 0.0f, h1 = 0.0f;                   // scalar pooling accums
#pragma unroll
        for (int tp = 0; tp < 6; tp++) {
            ulonglong2 ya = *reinterpret_cast<const ulonglong2*>(&ysp[nn * 24 + tp * 4]);
            ulonglong2 yb = *reinterpret_cast<const ulonglong2*>(&ysp[nn * 24 + tp * 4 + 2]);
            u64 az = ffma2(ya.x, mz0, bzp);
            u64 ah = ffma2(ya.x, mh0, bhp);
            az = ffma2(ya.y, mz1, az);
            ah = ffma2(ya.y, mh1, ah);
            az = ffma2(yb.x, mz2, az);
            ah = ffma2(yb.x, mh2, ah);
            az = ffma2(yb.y, mz3, az);
            ah = ffma2(yb.y, mh3, ah);
            float az0, az1, ah0, ah1;
            unpack2(az, az0, az1);
            unpack2(ah, ah0, ah1);
            float tz0 = tanh_fast(az0), th0 = tanh_fast(ah0);
            float tz1 = tanh_fast(az1), th1 = tanh_fast(ah1);
            float q0 = fmaf(-tz0, th0, th0);          // (1 - tz) * th
            float q1 = fmaf(-tz1, th1, th1);
            h0 = fmaf(phr[2 * tp],     q0, h0);
            h1 = fmaf(phr[2 * tp + 1], q1, h1);
        }
        float h = h0 + h1;
        hout[(size_t)(node0 + nn) * CC + c] = h;      // raw h output
        hs[nn * CC + c] = fmaxf(h, 0.0f);             // relu'd for MLP
    }

    if (!yout) return;
    __syncthreads();                                  // hs complete

    // ---- MLP layer 1: [16,256] @ [256,128]; 2 hid x 4 nodes per thread
    int ng   = tid >> 6;                              // node group 0..3 (4 nodes)
    int hidp = tid & 63;                              // hid base; also hid+64
    const float* hsg = hs + ng * 4 * CC;

    u64 accA[4], accB[4];
#pragma unroll
    for (int nn = 0; nn < 4; nn++) { accA[nn] = 0ull; accB[nn] = 0ull; }

#pragma unroll 2
    for (int k4 = 0; k4 < CC / 4; k4++) {
        ulonglong2 wa = g_W1p[k4 * HIDN + hidp];
        ulonglong2 wb = g_W1p[k4 * HIDN + hidp + 64];
#pragma unroll
        for (int nn = 0; nn < 4; nn++) {
            ulonglong2 hv = *reinterpret_cast<const ulonglong2*>(hsg + nn * CC + k4 * 4);
            accA[nn] = ffma2(hv.x, wa.x, accA[nn]);
            accA[nn] = ffma2(hv.y, wa.y, accA[nn]);
            accB[nn] = ffma2(hv.x, wb.x, accB[nn]);
            accB[nn] = ffma2(hv.y, wb.y, accB[nn]);
        }
    }

    float biasA = b1[hidp], biasB = b1[hidp + 64];
    float resA[4], resB[4];
#pragma unroll
    for (int nn = 0; nn < 4; nn++) {
        float lo, hi;
        unpack2(accA[nn], lo, hi);
        resA[nn] = fmaxf(lo + hi + biasA, 0.0f);
        unpack2(accB[nn], lo, hi);
        resB[nn] = fmaxf(lo + hi + biasB, 0.0f);
    }
    __syncthreads();                                  // hs reads done before alias
#pragma unroll
    for (int nn = 0; nn < 4; nn++) {
        s1[(ng * 4 + nn) * HIDN + hidp]      = resA[nn];
        s1[(ng * 4 + nn) * HIDN + hidp + 64] = resB[nn];
    }
    __syncthreads();

    // ---- MLP layer 2: 16 nodes x 12 outputs, float4 over k
    if (tid < NB * OUTN) {
        int node = tid / OUTN;
        int oo   = tid - node * OUTN;
        float a = b2[oo];
#pragma unroll
        for (int k4 = 0; k4 < HIDN / 4; k4++) {
            float4 sv = *reinterpret_cast<const float4*>(s1 + node * HIDN + k4 * 4);
            float4 wv = *reinterpret_cast<const float4*>(w2t + oo * HIDN + k4 * 4);
            a = fmaf(sv.x, wv.x, a);
            a = fmaf(sv.y, wv.y, a);
            a = fmaf(sv.z, wv.z, a);
            a = fmaf(sv.w, wv.w, a);
        }
        yout[(node0 + node) * OUTN + oo] = a;
    }
}

// ================================================================== host
extern "C" void kernel_launch(void* const* d_in, const int* in_sizes, int n_in,
                              void* d_out, int out_size) {
    const float* x = (const float*)d_in[0];
    RegPtrs rp;
    for (int r = 0; r < NREG; r++) {
        rp.ei[r] = (const int*)d_in[2 + r];     // IA,KS,KY,OH,WI edge_index
        rp.ew[r] = (const float*)d_in[7 + r];   // matching edge_attr
    }
    const float* Wc_z = (const float*)d_in[12];
    const float* bc_z = (const float*)d_in[13];
    const float* Wl_z = (const float*)d_in[14];
    const float* bl_z = (const float*)d_in[15];
    const float* Wc_h = (const float*)d_in[20];
    const float* bc_h = (const float*)d_in[21];
    const float* Wl_h = (const float*)d_in[22];
    const float* bl_h = (const float*)d_in[23];
    const float* att  = (const float*)d_in[24];
    const float* W1   = (const float*)d_in[25];
    const float* b1   = (const float*)d_in[26];
    const float* W2   = (const float*)d_in[27];
    const float* b2   = (const float*)d_in[28];

    float* out  = (float*)d_out;
    float* ydst = nullptr;
    float* hdst = nullptr;
    if (out_size >= NN * OUTN + NN * CC) { ydst = out; hdst = out + NN * OUTN; }
    else if (out_size >= NN * CC)        { hdst = out; }
    else                                 { ydst = out; }

    float* hbuf = hdst;
    if (!hbuf) {
        void* p = nullptr;
        cudaGetSymbolAddress(&p, g_h);
        hbuf = (float*)p;
    }

    k_init_w<<<2 + (NN * TT + 511) / 512, 512>>>(Wc_z, bc_z, Wl_z, bl_z,
                                                 Wc_h, bc_h, Wl_h, bl_h, att, W1);
    k_deg<<<(NREG * ERN + 255) / 256, 256>>>(rp);
    k_msg<<<(NREG * ERN + 255) / 256, 256>>>(x, rp);
    k_fused<<<NN / NB, 256>>>(x, b1, W2, b2, hbuf, ydst);
}